// round 1
// baseline (speedup 1.0000x reference)
#include <cuda_runtime.h>
#include <cuda_bf16.h>
#include <math.h>

// Problem constants
#define N_NODES   80000
#define N_EDGES   160000
#define HALF_E    80000
#define HID       300
#define NODE_DIM  133
#define EDGE_DIM  14
#define N_GRAPHS  1600
#define NN        300   // output columns of every GEMM

// ---------------------------------------------------------------------------
// Device scratch (static __device__ arrays; allocation-free per harness rules)
// ---------------------------------------------------------------------------
__device__ float g_h[(size_t)N_EDGES * HID];       // edge hidden state (192 MB)
__device__ float g_agg[(size_t)N_EDGES * HID];     // mp aggregation     (192 MB)
__device__ float g_nacc[(size_t)N_NODES * HID];    // per-node segsum    ( 96 MB)
__device__ float g_shared[(size_t)N_NODES * HID];  // shared conv output ( 96 MB)
__device__ float g_mu[(size_t)N_NODES * HID];      // mu conv output     ( 96 MB)
__device__ float g_lv[(size_t)N_NODES * HID];      // lv conv output     ( 96 MB)

__device__ int g_src[N_EDGES];
__device__ int g_dst[N_EDGES];
__device__ int g_deg[N_NODES];
__device__ int g_rowptr[N_NODES + 1];
__device__ int g_cursor[N_NODES];
__device__ int g_eidx[N_EDGES];
__device__ int g_gcnt[N_GRAPHS];
__device__ int g_gptr[N_GRAPHS + 1];

// ---------------------------------------------------------------------------
// Small utility kernels
// ---------------------------------------------------------------------------
__global__ void k_zero_int(int* p, int n) {
    int i = blockIdx.x * blockDim.x + threadIdx.x;
    if (i < n) p[i] = 0;
}

// build full edge lists: src = [src_half, dst_half], dst = [dst_half, src_half]
__global__ void k_edges(const int* __restrict__ sh, const int* __restrict__ dh,
                        int* __restrict__ src, int* __restrict__ dst, int half) {
    int i = blockIdx.x * blockDim.x + threadIdx.x;
    if (i < half) {
        int s = sh[i], d = dh[i];
        src[i] = s;        dst[i] = d;
        src[i + half] = d; dst[i + half] = s;
    }
}

__global__ void k_count(const int* __restrict__ key, int* __restrict__ cnt, int n) {
    int i = blockIdx.x * blockDim.x + threadIdx.x;
    if (i < n) atomicAdd(&cnt[key[i]], 1);
}

// single-block exclusive scan: out[0..n] (out[n] = total)
__global__ void k_scan(const int* __restrict__ in, int* __restrict__ out, int n) {
    __shared__ int sums[1024];
    int t = threadIdx.x;
    int chunk = (n + 1023) / 1024;
    int s = t * chunk;
    int e = s + chunk; if (e > n) e = n; if (s > n) s = n;
    int local = 0;
    for (int i = s; i < e; i++) local += in[i];
    sums[t] = local;
    __syncthreads();
    if (t == 0) {
        int run = 0;
        for (int i = 0; i < 1024; i++) { int v = sums[i]; sums[i] = run; run += v; }
        out[n] = run;
    }
    __syncthreads();
    int run = sums[t];
    for (int i = s; i < e; i++) { out[i] = run; run += in[i]; }
}

__global__ void k_fill_csr(const int* __restrict__ dst, int* __restrict__ cursor,
                           int* __restrict__ eidx, int n) {
    int e = blockIdx.x * blockDim.x + threadIdx.x;
    if (e < n) {
        int p = atomicAdd(&cursor[dst[e]], 1);
        eidx[p] = e;
    }
}

// node_acc[n][j] = sum over incoming edges e of h[e][j]   (CSR gather, no atomics)
__global__ void k_segsum(const float* __restrict__ h, const int* __restrict__ rowptr,
                         const int* __restrict__ eidx, float* __restrict__ out) {
    int node = blockIdx.x;
    int j = threadIdx.x;
    if (j >= NN) return;
    int s = rowptr[node], e = rowptr[node + 1];
    float sum = 0.f;
    for (int i = s; i < e; i++)
        sum += h[(size_t)eidx[i] * NN + j];
    out[(size_t)node * NN + j] = sum;
}

// agg[e][j] = nacc[src[e]][j] - h[rev(e)][j]
__global__ void k_agg(const float* __restrict__ nacc, const float* __restrict__ h,
                      const int* __restrict__ src, float* __restrict__ agg) {
    int e = blockIdx.x;
    int j = threadIdx.x;
    if (j >= NN) return;
    int re = (e < HALF_E) ? e + HALF_E : e - HALF_E;
    agg[(size_t)e * NN + j] = nacc[(size_t)src[e] * NN + j] - h[(size_t)re * NN + j];
}

// ---------------------------------------------------------------------------
// GEMM: C = act( [A or gathered-concat] @ B + bias (+ Cin) )
// MODE 0: A[r][k] = A[r*K + k]
// MODE 1: A[r][k] = (k < d1) ? X[idx[r]*d1 + k] : Y[r*d2 + (k-d1)]   (lin: gather)
// MODE 2: A[r][k] = (k < d1) ? X[r*d1 + k]      : Y[r*d2 + (k-d1)]   (atom update)
// 64x64 tile, BK=16, 256 threads, 4x4 per thread. Output is M x 300 row-major.
// ---------------------------------------------------------------------------
template <int MODE, bool RELU, bool ADD_C>
__global__ __launch_bounds__(256)
void k_gemm(const float* __restrict__ A, const float* __restrict__ X,
            const float* __restrict__ Y, const int* __restrict__ idx,
            int M, int K, int d1, int d2,
            const float* __restrict__ B, const float* __restrict__ bias,
            const float* __restrict__ Cin, float* __restrict__ Cout) {
    __shared__ float As[16][65];
    __shared__ float Bs[16][65];
    int tid = threadIdx.x;
    int row0 = blockIdx.y * 64;
    int col0 = blockIdx.x * 64;
    int ty = tid >> 4, tx = tid & 15;
    float acc[4][4] = {};

    for (int k0 = 0; k0 < K; k0 += 16) {
#pragma unroll
        for (int l = 0; l < 4; l++) {
            int lin = tid + 256 * l;
            int m = lin & 63, kk = lin >> 6;
            int r = row0 + m;
            int gk = k0 + kk;
            float va = 0.f;
            if (r < M && gk < K) {
                if (MODE == 0)      va = A[(size_t)r * K + gk];
                else if (MODE == 1) va = (gk < d1) ? X[(size_t)idx[r] * d1 + gk]
                                                   : Y[(size_t)r * d2 + (gk - d1)];
                else                va = (gk < d1) ? X[(size_t)r * d1 + gk]
                                                   : Y[(size_t)r * d2 + (gk - d1)];
            }
            As[kk][m] = va;
            int c = col0 + m;  // reuse m as column index for B tile
            float vb = 0.f;
            if (gk < K && c < NN) vb = B[(size_t)gk * NN + c];
            Bs[kk][m] = vb;
        }
        __syncthreads();
#pragma unroll
        for (int kk = 0; kk < 16; kk++) {
            float ra[4], rb[4];
#pragma unroll
            for (int i = 0; i < 4; i++) ra[i] = As[kk][ty * 4 + i];
#pragma unroll
            for (int j = 0; j < 4; j++) rb[j] = Bs[kk][tx * 4 + j];
#pragma unroll
            for (int i = 0; i < 4; i++)
#pragma unroll
                for (int j = 0; j < 4; j++)
                    acc[i][j] += ra[i] * rb[j];
        }
        __syncthreads();
    }

#pragma unroll
    for (int i = 0; i < 4; i++) {
        int r = row0 + ty * 4 + i;
        if (r >= M) continue;
#pragma unroll
        for (int j = 0; j < 4; j++) {
            int c = col0 + tx * 4 + j;
            if (c >= NN) continue;
            float v = acc[i][j] + bias[c];
            if (ADD_C) v += Cin[(size_t)r * NN + c];
            if (RELU) v = fmaxf(v, 0.f);
            Cout[(size_t)r * NN + c] = v;
        }
    }
}

// ---------------------------------------------------------------------------
// Final pooling: z[g][j] = mu_g + exp(0.5*lv_g)*eps
// ---------------------------------------------------------------------------
__global__ void k_pool(const float* __restrict__ mu, const float* __restrict__ lv,
                       const float* __restrict__ w, const float* __restrict__ eps,
                       const int* __restrict__ gptr, float* __restrict__ out) {
    int g = blockIdx.x;
    int j = threadIdx.x;
    if (j >= NN) return;
    int s = gptr[g], e = gptr[g + 1];
    float ms = 0.f, ls = 0.f;
    for (int n = s; n < e; n++) {
        float ww = w[n];
        ms += mu[(size_t)n * NN + j] * ww;
        ls += lv[(size_t)n * NN + j] * ww;
    }
    float c = fmaxf((float)(e - s), 1.f);
    out[(size_t)g * NN + j] = ms / c + expf(0.5f * ls / c) * eps[(size_t)g * NN + j];
}

// ---------------------------------------------------------------------------
// Host orchestration
// ---------------------------------------------------------------------------
static void* sym(const void* s) {
    void* p = nullptr;
    cudaGetSymbolAddress(&p, (const void*)s);
    return p;
}

extern "C" void kernel_launch(void* const* d_in, const int* in_sizes, int n_in,
                              void* d_out, int out_size) {
    const float* x         = (const float*)d_in[0];
    const float* edge_attr = (const float*)d_in[1];
    const float* W_atoms   = (const float*)d_in[2];
    const float* eps       = (const float*)d_in[3];
    const int*   src_half  = (const int*)d_in[4];
    const int*   dst_half  = (const int*)d_in[5];
    const int*   batch     = (const int*)d_in[6];
    const float* t_lin_w   = (const float*)d_in[7];
    const float* t_lin_b   = (const float*)d_in[8];
    const float* t_mp_w    = (const float*)d_in[9];
    const float* t_mp_b    = (const float*)d_in[10];
    const float* t_au_w    = (const float*)d_in[11];
    const float* t_au_b    = (const float*)d_in[12];
    const float* mu_lin_w  = (const float*)d_in[13];
    const float* mu_lin_b  = (const float*)d_in[14];
    const float* mu_mp_w   = (const float*)d_in[15];
    const float* mu_mp_b   = (const float*)d_in[16];
    const float* mu_au_w   = (const float*)d_in[17];
    const float* mu_au_b   = (const float*)d_in[18];
    const float* lv_lin_w  = (const float*)d_in[19];
    const float* lv_lin_b  = (const float*)d_in[20];
    const float* lv_mp_w   = (const float*)d_in[21];
    const float* lv_mp_b   = (const float*)d_in[22];
    const float* lv_au_w   = (const float*)d_in[23];
    const float* lv_au_b   = (const float*)d_in[24];
    float* out = (float*)d_out;
    (void)in_sizes; (void)n_in; (void)out_size;

    float* h      = (float*)sym(g_h);
    float* agg    = (float*)sym(g_agg);
    float* nacc   = (float*)sym(g_nacc);
    float* shrd   = (float*)sym(g_shared);
    float* mu     = (float*)sym(g_mu);
    float* lv     = (float*)sym(g_lv);
    int* src      = (int*)sym(g_src);
    int* dst      = (int*)sym(g_dst);
    int* deg      = (int*)sym(g_deg);
    int* rowptr   = (int*)sym(g_rowptr);
    int* cursor   = (int*)sym(g_cursor);
    int* eidx     = (int*)sym(g_eidx);
    int* gcnt     = (int*)sym(g_gcnt);
    int* gptr     = (int*)sym(g_gptr);

    const int TPB = 256;

    // ---- CSR build (incoming edges per node) ----
    k_edges<<<(HALF_E + TPB - 1) / TPB, TPB>>>(src_half, dst_half, src, dst, HALF_E);
    k_zero_int<<<(N_NODES + TPB - 1) / TPB, TPB>>>(deg, N_NODES);
    k_count<<<(N_EDGES + TPB - 1) / TPB, TPB>>>(dst, deg, N_EDGES);
    k_scan<<<1, 1024>>>(deg, rowptr, N_NODES);
    cudaMemcpyAsync(cursor, rowptr, N_NODES * sizeof(int), cudaMemcpyDeviceToDevice);
    k_fill_csr<<<(N_EDGES + TPB - 1) / TPB, TPB>>>(dst, cursor, eidx, N_EDGES);

    // ---- graph segment offsets (batch is sorted) ----
    k_zero_int<<<(N_GRAPHS + TPB - 1) / TPB, TPB>>>(gcnt, N_GRAPHS);
    k_count<<<(N_NODES + TPB - 1) / TPB, TPB>>>(batch, gcnt, N_NODES);
    k_scan<<<1, 1024>>>(gcnt, gptr, N_GRAPHS);

    dim3 gridE((NN + 63) / 64, (N_EDGES + 63) / 64);
    dim3 gridN((NN + 63) / 64, (N_NODES + 63) / 64);

    // ---- one conv layer ----
    auto conv = [&](const float* node_in, int dnode,
                    const float* lin_w, const float* lin_b,
                    const float* mp_w, const float* mp_b,
                    const float* au_w, const float* au_b,
                    float* outbuf, bool out_relu) {
        // h = relu([node_in[src], edge_attr] @ lin_w + lin_b)
        k_gemm<1, true, false><<<gridE, 256>>>(
            nullptr, node_in, edge_attr, src,
            N_EDGES, dnode + EDGE_DIM, dnode, EDGE_DIM,
            lin_w, lin_b, nullptr, h);

        for (int i = 0; i < 3; i++) {
            k_segsum<<<N_NODES, 320>>>(h, rowptr, eidx, nacc);
            k_agg<<<N_EDGES, 320>>>(nacc, h, src, agg);
            // h = relu(h + agg @ mp_w[i] + mp_b[i])   (in-place safe)
            k_gemm<0, true, true><<<gridE, 256>>>(
                agg, nullptr, nullptr, nullptr,
                N_EDGES, HID, 0, 0,
                mp_w + (size_t)i * HID * HID, mp_b + (size_t)i * HID, h, h);
        }

        // sum_inc -> nacc; out = act([node_in, sum_inc] @ au_w + au_b)
        k_segsum<<<N_NODES, 320>>>(h, rowptr, eidx, nacc);
        if (out_relu)
            k_gemm<2, true, false><<<gridN, 256>>>(
                nullptr, node_in, nacc, nullptr,
                N_NODES, dnode + HID, dnode, HID,
                au_w, au_b, nullptr, outbuf);
        else
            k_gemm<2, false, false><<<gridN, 256>>>(
                nullptr, node_in, nacc, nullptr,
                N_NODES, dnode + HID, dnode, HID,
                au_w, au_b, nullptr, outbuf);
    };

    conv(x,    NODE_DIM, t_lin_w,  t_lin_b,  t_mp_w,  t_mp_b,  t_au_w,  t_au_b,  shrd, true);
    conv(shrd, HID,      mu_lin_w, mu_lin_b, mu_mp_w, mu_mp_b, mu_au_w, mu_au_b, mu,   false);
    conv(shrd, HID,      lv_lin_w, lv_lin_b, lv_mp_w, lv_mp_b, lv_au_w, lv_au_b, lv,   false);

    k_pool<<<N_GRAPHS, 320>>>(mu, lv, W_atoms, eps, gptr, out);
}

// round 2
// speedup vs baseline: 1.2763x; 1.2763x over previous
#include <cuda_runtime.h>
#include <cuda_bf16.h>
#include <math.h>
#include <stdint.h>

// Problem constants
#define N_NODES   80000
#define N_EDGES   160000
#define HALF_E    80000
#define HID       300
#define NODE_DIM  133
#define EDGE_DIM  14
#define N_GRAPHS  1600
#define NN        300   // output columns of every GEMM

// ---------------------------------------------------------------------------
// Device scratch (static __device__ arrays; allocation-free per harness rules)
// ---------------------------------------------------------------------------
__device__ float g_h[(size_t)N_EDGES * HID];       // edge hidden state (192 MB)
__device__ float g_agg[(size_t)N_EDGES * HID];     // mp aggregation     (192 MB)
__device__ float g_nacc[(size_t)N_NODES * HID];    // per-node segsum    ( 96 MB)
__device__ float g_shared[(size_t)N_NODES * HID];  // shared conv output ( 96 MB)
__device__ float g_mu[(size_t)N_NODES * HID];      // mu conv output     ( 96 MB)
__device__ float g_lv[(size_t)N_NODES * HID];      // lv conv output     ( 96 MB)

__device__ int g_src[N_EDGES];
__device__ int g_dst[N_EDGES];
__device__ int g_deg[N_NODES];
__device__ int g_rowptr[N_NODES + 1];
__device__ int g_cursor[N_NODES];
__device__ int g_eidx[N_EDGES];
__device__ int g_gcnt[N_GRAPHS];
__device__ int g_gptr[N_GRAPHS + 1];

// ---------------------------------------------------------------------------
// Small utility kernels
// ---------------------------------------------------------------------------
__global__ void k_zero_int(int* p, int n) {
    int i = blockIdx.x * blockDim.x + threadIdx.x;
    if (i < n) p[i] = 0;
}

__global__ void k_edges(const int* __restrict__ sh, const int* __restrict__ dh,
                        int* __restrict__ src, int* __restrict__ dst, int half) {
    int i = blockIdx.x * blockDim.x + threadIdx.x;
    if (i < half) {
        int s = sh[i], d = dh[i];
        src[i] = s;        dst[i] = d;
        src[i + half] = d; dst[i + half] = s;
    }
}

__global__ void k_count(const int* __restrict__ key, int* __restrict__ cnt, int n) {
    int i = blockIdx.x * blockDim.x + threadIdx.x;
    if (i < n) atomicAdd(&cnt[key[i]], 1);
}

// single-block exclusive scan: out[0..n] (out[n] = total)
__global__ void k_scan(const int* __restrict__ in, int* __restrict__ out, int n) {
    __shared__ int sums[1024];
    int t = threadIdx.x;
    int chunk = (n + 1023) / 1024;
    int s = t * chunk;
    int e = s + chunk; if (e > n) e = n; if (s > n) s = n;
    int local = 0;
    for (int i = s; i < e; i++) local += in[i];
    sums[t] = local;
    __syncthreads();
    if (t == 0) {
        int run = 0;
        for (int i = 0; i < 1024; i++) { int v = sums[i]; sums[i] = run; run += v; }
        out[n] = run;
    }
    __syncthreads();
    int run = sums[t];
    for (int i = s; i < e; i++) { out[i] = run; run += in[i]; }
}

__global__ void k_fill_csr(const int* __restrict__ dst, int* __restrict__ cursor,
                           int* __restrict__ eidx, int n) {
    int e = blockIdx.x * blockDim.x + threadIdx.x;
    if (e < n) {
        int p = atomicAdd(&cursor[dst[e]], 1);
        eidx[p] = e;
    }
}

// node_acc[n][j] = sum over incoming edges e of h[e][j]   (CSR gather, no atomics)
__global__ void k_segsum(const float* __restrict__ h, const int* __restrict__ rowptr,
                         const int* __restrict__ eidx, float* __restrict__ out) {
    int node = blockIdx.x;
    int j = threadIdx.x;
    if (j >= NN) return;
    int s = rowptr[node], e = rowptr[node + 1];
    float sum = 0.f;
    for (int i = s; i < e; i++)
        sum += h[(size_t)eidx[i] * NN + j];
    out[(size_t)node * NN + j] = sum;
}

// agg[e][j] = nacc[src[e]][j] - h[rev(e)][j]
__global__ void k_agg(const float* __restrict__ nacc, const float* __restrict__ h,
                      const int* __restrict__ src, float* __restrict__ agg) {
    int e = blockIdx.x;
    int j = threadIdx.x;
    if (j >= NN) return;
    int re = (e < HALF_E) ? e + HALF_E : e - HALF_E;
    agg[(size_t)e * NN + j] = nacc[(size_t)src[e] * NN + j] - h[(size_t)re * NN + j];
}

// ---------------------------------------------------------------------------
// TF32 tensor-core GEMM with 3xTF32 split (near-fp32 accuracy).
// C = act( [A or gathered-concat] @ B + bias (+ Cin) )
// MODE 0: A[r][k] = A[r*K + k]
// MODE 1: A[r][k] = (k < d1) ? X[idx[r]*d1 + k] : Y[r*d2 + (k-d1)]
// MODE 2: A[r][k] = (k < d1) ? X[r*d1 + k]      : Y[r*d2 + (k-d1)]
// Block tile 128x64, BK=32, 256 threads (8 warps, 4x2 of 32x32 warp tiles).
// M must be a multiple of 128 (true here: 160000 and 80000).
// ---------------------------------------------------------------------------
__device__ __forceinline__ uint32_t f2tf32(float x) {
    uint32_t r;
    asm("cvt.rna.tf32.f32 %0, %1;" : "=r"(r) : "f"(x));
    return r;
}

__device__ __forceinline__ void mma8(float* c, const uint32_t* a, const uint32_t* b) {
    asm volatile(
        "mma.sync.aligned.m16n8k8.row.col.f32.tf32.tf32.f32 "
        "{%0,%1,%2,%3}, {%4,%5,%6,%7}, {%8,%9}, {%0,%1,%2,%3};\n"
        : "+f"(c[0]), "+f"(c[1]), "+f"(c[2]), "+f"(c[3])
        : "r"(a[0]), "r"(a[1]), "r"(a[2]), "r"(a[3]), "r"(b[0]), "r"(b[1]));
}

template <int MODE, bool RELU, bool ADD_C>
__global__ __launch_bounds__(256, 2)
void k_gemm_tc(const float* __restrict__ A, const float* __restrict__ X,
               const float* __restrict__ Y, const int* __restrict__ idx,
               int M, int K, int d1, int d2,
               const float* __restrict__ B, const float* __restrict__ bias,
               const float* __restrict__ Cin, float* __restrict__ Cout) {
    __shared__ float As[128][36];  // row-major, pad 36 -> a-frag loads conflict-free
    __shared__ float Bs[32][68];   // [k][n], pad 68

    const int tid  = threadIdx.x;
    const int warp = tid >> 5;
    const int lane = tid & 31;
    const int wm = (warp >> 1) * 32;   // warp m offset: 0,32,64,96
    const int wn = (warp & 1) * 32;    // warp n offset: 0,32
    const int row0 = blockIdx.y * 128;
    const int col0 = blockIdx.x * 64;
    const int lq = lane >> 2;          // 0..7
    const int lr = lane & 3;           // 0..3

    float acc[2][4][4];
#pragma unroll
    for (int mf = 0; mf < 2; mf++)
#pragma unroll
        for (int nf = 0; nf < 4; nf++)
#pragma unroll
            for (int i = 0; i < 4; i++) acc[mf][nf][i] = 0.f;

    for (int k0 = 0; k0 < K; k0 += 32) {
        // ---- load A tile: 128 x 32, 16 elems/thread, coalesced along k ----
        {
            const int kk = tid & 31;
            const int gk = k0 + kk;
            const bool kok = (gk < K);
#pragma unroll
            for (int p = 0; p < 16; p++) {
                int m = (tid >> 5) + p * 8;
                int r = row0 + m;
                float v = 0.f;
                if (kok) {
                    if (MODE == 0)      v = A[(size_t)r * K + gk];
                    else if (MODE == 1) v = (gk < d1) ? X[(size_t)idx[r] * d1 + gk]
                                                      : Y[(size_t)r * d2 + (gk - d1)];
                    else                v = (gk < d1) ? X[(size_t)r * d1 + gk]
                                                      : Y[(size_t)r * d2 + (gk - d1)];
                }
                As[m][kk] = v;
            }
        }
        // ---- load B tile: 32 x 64, 8 elems/thread, coalesced along n ----
        {
            const int n = tid & 63;
            const int c = col0 + n;
#pragma unroll
            for (int p = 0; p < 8; p++) {
                int kk = (tid >> 6) + p * 4;
                int gk = k0 + kk;
                float v = 0.f;
                if (gk < K && c < NN) v = B[(size_t)gk * NN + c];
                Bs[kk][n] = v;
            }
        }
        __syncthreads();

#pragma unroll
        for (int ks = 0; ks < 4; ks++) {
            const int kb = ks * 8;
            uint32_t ahi[2][4], alo[2][4];
#pragma unroll
            for (int mf = 0; mf < 2; mf++) {
#pragma unroll
                for (int i = 0; i < 4; i++) {
                    int rr = wm + mf * 16 + lq + (i & 1) * 8;
                    int cc = kb + lr + (i >> 1) * 4;
                    float a = As[rr][cc];
                    uint32_t h = f2tf32(a);
                    ahi[mf][i] = h;
                    alo[mf][i] = f2tf32(a - __uint_as_float(h));
                }
            }
            uint32_t bhi[4][2], blo[4][2];
#pragma unroll
            for (int nf = 0; nf < 4; nf++) {
#pragma unroll
                for (int i = 0; i < 2; i++) {
                    int kk = kb + lr + i * 4;
                    int nn = wn + nf * 8 + lq;
                    float b = Bs[kk][nn];
                    uint32_t h = f2tf32(b);
                    bhi[nf][i] = h;
                    blo[nf][i] = f2tf32(b - __uint_as_float(h));
                }
            }
#pragma unroll
            for (int mf = 0; mf < 2; mf++)
#pragma unroll
                for (int nf = 0; nf < 4; nf++) {
                    mma8(acc[mf][nf], ahi[mf], bhi[nf]);
                    mma8(acc[mf][nf], ahi[mf], blo[nf]);
                    mma8(acc[mf][nf], alo[mf], bhi[nf]);
                }
        }
        __syncthreads();
    }

    // ---- epilogue: bias (+Cin) (+relu), float2 stores ----
#pragma unroll
    for (int mf = 0; mf < 2; mf++) {
#pragma unroll
        for (int nf = 0; nf < 4; nf++) {
            int c = col0 + wn + nf * 8 + 2 * lr;
            if (c >= NN) continue;
            float b0 = bias[c], b1 = bias[c + 1];
#pragma unroll
            for (int half = 0; half < 2; half++) {
                int r = row0 + wm + mf * 16 + lq + half * 8;
                float v0 = acc[mf][nf][half * 2 + 0] + b0;
                float v1 = acc[mf][nf][half * 2 + 1] + b1;
                if (ADD_C) {
                    const float2 ci = *(const float2*)&Cin[(size_t)r * NN + c];
                    v0 += ci.x; v1 += ci.y;
                }
                if (RELU) { v0 = fmaxf(v0, 0.f); v1 = fmaxf(v1, 0.f); }
                *(float2*)&Cout[(size_t)r * NN + c] = make_float2(v0, v1);
            }
        }
    }
}

// ---------------------------------------------------------------------------
// Final pooling: z[g][j] = mu_g + exp(0.5*lv_g)*eps
// ---------------------------------------------------------------------------
__global__ void k_pool(const float* __restrict__ mu, const float* __restrict__ lv,
                       const float* __restrict__ w, const float* __restrict__ eps,
                       const int* __restrict__ gptr, float* __restrict__ out) {
    int g = blockIdx.x;
    int j = threadIdx.x;
    if (j >= NN) return;
    int s = gptr[g], e = gptr[g + 1];
    float ms = 0.f, ls = 0.f;
    for (int n = s; n < e; n++) {
        float ww = w[n];
        ms += mu[(size_t)n * NN + j] * ww;
        ls += lv[(size_t)n * NN + j] * ww;
    }
    float c = fmaxf((float)(e - s), 1.f);
    out[(size_t)g * NN + j] = ms / c + expf(0.5f * ls / c) * eps[(size_t)g * NN + j];
}

// ---------------------------------------------------------------------------
// Host orchestration
// ---------------------------------------------------------------------------
static void* sym(const void* s) {
    void* p = nullptr;
    cudaGetSymbolAddress(&p, (const void*)s);
    return p;
}

extern "C" void kernel_launch(void* const* d_in, const int* in_sizes, int n_in,
                              void* d_out, int out_size) {
    const float* x         = (const float*)d_in[0];
    const float* edge_attr = (const float*)d_in[1];
    const float* W_atoms   = (const float*)d_in[2];
    const float* eps       = (const float*)d_in[3];
    const int*   src_half  = (const int*)d_in[4];
    const int*   dst_half  = (const int*)d_in[5];
    const int*   batch     = (const int*)d_in[6];
    const float* t_lin_w   = (const float*)d_in[7];
    const float* t_lin_b   = (const float*)d_in[8];
    const float* t_mp_w    = (const float*)d_in[9];
    const float* t_mp_b    = (const float*)d_in[10];
    const float* t_au_w    = (const float*)d_in[11];
    const float* t_au_b    = (const float*)d_in[12];
    const float* mu_lin_w  = (const float*)d_in[13];
    const float* mu_lin_b  = (const float*)d_in[14];
    const float* mu_mp_w   = (const float*)d_in[15];
    const float* mu_mp_b   = (const float*)d_in[16];
    const float* mu_au_w   = (const float*)d_in[17];
    const float* mu_au_b   = (const float*)d_in[18];
    const float* lv_lin_w  = (const float*)d_in[19];
    const float* lv_lin_b  = (const float*)d_in[20];
    const float* lv_mp_w   = (const float*)d_in[21];
    const float* lv_mp_b   = (const float*)d_in[22];
    const float* lv_au_w   = (const float*)d_in[23];
    const float* lv_au_b   = (const float*)d_in[24];
    float* out = (float*)d_out;
    (void)in_sizes; (void)n_in; (void)out_size;

    float* h      = (float*)sym(g_h);
    float* agg    = (float*)sym(g_agg);
    float* nacc   = (float*)sym(g_nacc);
    float* shrd   = (float*)sym(g_shared);
    float* mu     = (float*)sym(g_mu);
    float* lv     = (float*)sym(g_lv);
    int* src      = (int*)sym(g_src);
    int* dst      = (int*)sym(g_dst);
    int* deg      = (int*)sym(g_deg);
    int* rowptr   = (int*)sym(g_rowptr);
    int* cursor   = (int*)sym(g_cursor);
    int* eidx     = (int*)sym(g_eidx);
    int* gcnt     = (int*)sym(g_gcnt);
    int* gptr     = (int*)sym(g_gptr);

    const int TPB = 256;

    // ---- CSR build (incoming edges per node) ----
    k_edges<<<(HALF_E + TPB - 1) / TPB, TPB>>>(src_half, dst_half, src, dst, HALF_E);
    k_zero_int<<<(N_NODES + TPB - 1) / TPB, TPB>>>(deg, N_NODES);
    k_count<<<(N_EDGES + TPB - 1) / TPB, TPB>>>(dst, deg, N_EDGES);
    k_scan<<<1, 1024>>>(deg, rowptr, N_NODES);
    cudaMemcpyAsync(cursor, rowptr, N_NODES * sizeof(int), cudaMemcpyDeviceToDevice);
    k_fill_csr<<<(N_EDGES + TPB - 1) / TPB, TPB>>>(dst, cursor, eidx, N_EDGES);

    // ---- graph segment offsets (batch is sorted) ----
    k_zero_int<<<(N_GRAPHS + TPB - 1) / TPB, TPB>>>(gcnt, N_GRAPHS);
    k_count<<<(N_NODES + TPB - 1) / TPB, TPB>>>(batch, gcnt, N_NODES);
    k_scan<<<1, 1024>>>(gcnt, gptr, N_GRAPHS);

    dim3 gridE((NN + 63) / 64, N_EDGES / 128);   // x = col tiles (fast) -> L2 reuse of A
    dim3 gridN((NN + 63) / 64, N_NODES / 128);

    // ---- one conv layer ----
    auto conv = [&](const float* node_in, int dnode,
                    const float* lin_w, const float* lin_b,
                    const float* mp_w, const float* mp_b,
                    const float* au_w, const float* au_b,
                    float* outbuf, bool out_relu) {
        // h = relu([node_in[src], edge_attr] @ lin_w + lin_b)
        k_gemm_tc<1, true, false><<<gridE, 256>>>(
            nullptr, node_in, edge_attr, src,
            N_EDGES, dnode + EDGE_DIM, dnode, EDGE_DIM,
            lin_w, lin_b, nullptr, h);

        for (int i = 0; i < 3; i++) {
            k_segsum<<<N_NODES, 320>>>(h, rowptr, eidx, nacc);
            k_agg<<<N_EDGES, 320>>>(nacc, h, src, agg);
            // h = relu(h + agg @ mp_w[i] + mp_b[i])   (in-place safe)
            k_gemm_tc<0, true, true><<<gridE, 256>>>(
                agg, nullptr, nullptr, nullptr,
                N_EDGES, HID, 0, 0,
                mp_w + (size_t)i * HID * HID, mp_b + (size_t)i * HID, h, h);
        }

        // sum_inc -> nacc; out = act([node_in, sum_inc] @ au_w + au_b)
        k_segsum<<<N_NODES, 320>>>(h, rowptr, eidx, nacc);
        if (out_relu)
            k_gemm_tc<2, true, false><<<gridN, 256>>>(
                nullptr, node_in, nacc, nullptr,
                N_NODES, dnode + HID, dnode, HID,
                au_w, au_b, nullptr, outbuf);
        else
            k_gemm_tc<2, false, false><<<gridN, 256>>>(
                nullptr, node_in, nacc, nullptr,
                N_NODES, dnode + HID, dnode, HID,
                au_w, au_b, nullptr, outbuf);
    };

    conv(x,    NODE_DIM, t_lin_w,  t_lin_b,  t_mp_w,  t_mp_b,  t_au_w,  t_au_b,  shrd, true);
    conv(shrd, HID,      mu_lin_w, mu_lin_b, mu_mp_w, mu_mp_b, mu_au_w, mu_au_b, mu,   false);
    conv(shrd, HID,      lv_lin_w, lv_lin_b, lv_mp_w, lv_mp_b, lv_au_w, lv_au_b, lv,   false);

    k_pool<<<N_GRAPHS, 320>>>(mu, lv, W_atoms, eps, gptr, out);
}

// round 3
// speedup vs baseline: 1.3829x; 1.0835x over previous
#include <cuda_runtime.h>
#include <cuda_bf16.h>
#include <math.h>
#include <stdint.h>

// Problem constants
#define N_NODES   80000
#define N_EDGES   160000
#define HALF_E    80000
#define HID       300
#define NODE_DIM  133
#define EDGE_DIM  14
#define N_GRAPHS  1600
#define NN        300   // output columns of every GEMM

// ---------------------------------------------------------------------------
// Device scratch
// ---------------------------------------------------------------------------
__device__ float g_h[(size_t)N_EDGES * HID];       // edge hidden state (ping)
__device__ float g_h2[(size_t)N_EDGES * HID];      // edge hidden state (pong)
__device__ float g_nacc[(size_t)N_NODES * HID];    // per-node segsum
__device__ float g_shared[(size_t)N_NODES * HID];  // shared conv output
__device__ float g_mu[(size_t)N_NODES * HID];
__device__ float g_lv[(size_t)N_NODES * HID];

__device__ int g_src[N_EDGES];
__device__ int g_dst[N_EDGES];
__device__ int g_deg[N_NODES];
__device__ int g_rowptr[N_NODES + 1];
__device__ int g_cursor[N_NODES];
__device__ int g_eidx[N_EDGES];
__device__ int g_gcnt[N_GRAPHS];
__device__ int g_gptr[N_GRAPHS + 1];

// ---------------------------------------------------------------------------
// Small utility kernels
// ---------------------------------------------------------------------------
__global__ void k_zero_int(int* p, int n) {
    int i = blockIdx.x * blockDim.x + threadIdx.x;
    if (i < n) p[i] = 0;
}

__global__ void k_edges(const int* __restrict__ sh, const int* __restrict__ dh,
                        int* __restrict__ src, int* __restrict__ dst, int half) {
    int i = blockIdx.x * blockDim.x + threadIdx.x;
    if (i < half) {
        int s = sh[i], d = dh[i];
        src[i] = s;        dst[i] = d;
        src[i + half] = d; dst[i + half] = s;
    }
}

__global__ void k_count(const int* __restrict__ key, int* __restrict__ cnt, int n) {
    int i = blockIdx.x * blockDim.x + threadIdx.x;
    if (i < n) atomicAdd(&cnt[key[i]], 1);
}

// single-block exclusive scan: out[0..n] (out[n] = total)
__global__ void k_scan(const int* __restrict__ in, int* __restrict__ out, int n) {
    __shared__ int sums[1024];
    int t = threadIdx.x;
    int chunk = (n + 1023) / 1024;
    int s = t * chunk;
    int e = s + chunk; if (e > n) e = n; if (s > n) s = n;
    int local = 0;
    for (int i = s; i < e; i++) local += in[i];
    sums[t] = local;
    __syncthreads();
    if (t == 0) {
        int run = 0;
        for (int i = 0; i < 1024; i++) { int v = sums[i]; sums[i] = run; run += v; }
        out[n] = run;
    }
    __syncthreads();
    int run = sums[t];
    for (int i = s; i < e; i++) { out[i] = run; run += in[i]; }
}

__global__ void k_fill_csr(const int* __restrict__ dst, int* __restrict__ cursor,
                           int* __restrict__ eidx, int n) {
    int e = blockIdx.x * blockDim.x + threadIdx.x;
    if (e < n) {
        int p = atomicAdd(&cursor[dst[e]], 1);
        eidx[p] = e;
    }
}

// node_acc[n][j] = sum over incoming edges e of h[e][j]   (CSR gather, no atomics)
__global__ void k_segsum(const float* __restrict__ h, const int* __restrict__ rowptr,
                         const int* __restrict__ eidx, float* __restrict__ out) {
    int node = blockIdx.x;
    int j = threadIdx.x;
    if (j >= NN) return;
    int s = rowptr[node], e = rowptr[node + 1];
    float sum = 0.f;
    for (int i = s; i < e; i++)
        sum += h[(size_t)eidx[i] * NN + j];
    out[(size_t)node * NN + j] = sum;
}

// ---------------------------------------------------------------------------
// TF32 tensor-core GEMM, 3xTF32 split hoisted to smem-load time.
// C = act( A' @ B + bias (+ Cin) )
// MODE 1: A'[r][k] = (k < d1) ? X[idx[r]*d1 + k] : Y[r*d2 + (k-d1)]    (lin)
// MODE 2: A'[r][k] = (k < d1) ? X[r*d1 + k]      : Y[r*d2 + (k-d1)]    (atom upd)
// MODE 3: A'[r][k] = X[idx[r]*NN + k] - Y[rev(r)*NN + k]               (mp agg)
// Smem tiles hold packed {tf32_hi, tf32_lo} as uint2; inner loop is LDS.64+MMA.
// Block tile 128x64, BK=32, 256 threads (8 warps, 4x2 of 32x32 warp tiles).
// M must be a multiple of 128.
// ---------------------------------------------------------------------------
#define PA 36   // A row pitch in uint2 (2*36 % 32 == 8 -> conflict-free frags)
#define PB 68   // B row pitch in uint2 (2*68 % 32 == 8)
#define GEMM_SMEM ((128 * PA + 32 * PB) * (int)sizeof(uint2))

__device__ __forceinline__ uint32_t f2tf32(float x) {
    uint32_t r;
    asm("cvt.rna.tf32.f32 %0, %1;" : "=r"(r) : "f"(x));
    return r;
}
__device__ __forceinline__ uint2 split_tf32(float a) {
    uint32_t hi = f2tf32(a);
    uint32_t lo = f2tf32(a - __uint_as_float(hi));
    return make_uint2(hi, lo);
}

__device__ __forceinline__ void mma8(float* c, const uint32_t* a, const uint32_t* b) {
    asm volatile(
        "mma.sync.aligned.m16n8k8.row.col.f32.tf32.tf32.f32 "
        "{%0,%1,%2,%3}, {%4,%5,%6,%7}, {%8,%9}, {%0,%1,%2,%3};\n"
        : "+f"(c[0]), "+f"(c[1]), "+f"(c[2]), "+f"(c[3])
        : "r"(a[0]), "r"(a[1]), "r"(a[2]), "r"(a[3]), "r"(b[0]), "r"(b[1]));
}

template <int MODE, bool RELU, bool ADD_C>
__global__ __launch_bounds__(256, 2)
void k_gemm_tc(const float* __restrict__ X,
               const float* __restrict__ Y, const int* __restrict__ idx,
               int M, int K, int d1, int d2,
               const float* __restrict__ B, const float* __restrict__ bias,
               const float* __restrict__ Cin, float* __restrict__ Cout) {
    extern __shared__ uint2 smem[];
    uint2* As = smem;              // [128][PA]
    uint2* Bs = smem + 128 * PA;   // [32][PB]

    const int tid  = threadIdx.x;
    const int warp = tid >> 5;
    const int lane = tid & 31;
    const int wm = (warp >> 1) * 32;
    const int wn = (warp & 1) * 32;
    const int row0 = blockIdx.y * 128;
    const int col0 = blockIdx.x * 64;
    const int lq = lane >> 2;
    const int lr = lane & 3;

    float acc[2][4][4];
#pragma unroll
    for (int mf = 0; mf < 2; mf++)
#pragma unroll
        for (int nf = 0; nf < 4; nf++)
#pragma unroll
            for (int i = 0; i < 4; i++) acc[mf][nf][i] = 0.f;

    for (int k0 = 0; k0 < K; k0 += 32) {
        // ---- load + split A tile: 128 x 32 ----
        {
            const int kk = tid & 31;
            const int gk = k0 + kk;
            const bool kok = (gk < K);
#pragma unroll
            for (int p = 0; p < 16; p++) {
                int m = (tid >> 5) + p * 8;
                int r = row0 + m;
                float v = 0.f;
                if (kok) {
                    if (MODE == 1)      v = (gk < d1) ? X[(size_t)idx[r] * d1 + gk]
                                                      : Y[(size_t)r * d2 + (gk - d1)];
                    else if (MODE == 2) v = (gk < d1) ? X[(size_t)r * d1 + gk]
                                                      : Y[(size_t)r * d2 + (gk - d1)];
                    else {  // MODE 3: agg fused
                        int re = (r < HALF_E) ? r + HALF_E : r - HALF_E;
                        v = X[(size_t)idx[r] * NN + gk] - Y[(size_t)re * NN + gk];
                    }
                }
                As[m * PA + kk] = split_tf32(v);
            }
        }
        // ---- load + split B tile: 32 x 64 ----
        {
            const int n = tid & 63;
            const int c = col0 + n;
#pragma unroll
            for (int p = 0; p < 8; p++) {
                int kk = (tid >> 6) + p * 4;
                int gk = k0 + kk;
                float v = 0.f;
                if (gk < K && c < NN) v = B[(size_t)gk * NN + c];
                Bs[kk * PB + n] = split_tf32(v);
            }
        }
        __syncthreads();

#pragma unroll
        for (int ks = 0; ks < 4; ks++) {
            const int kb = ks * 8;
            uint32_t ahi[2][4], alo[2][4];
#pragma unroll
            for (int mf = 0; mf < 2; mf++) {
#pragma unroll
                for (int i = 0; i < 4; i++) {
                    int rr = wm + mf * 16 + lq + (i & 1) * 8;
                    int cc = kb + lr + (i >> 1) * 4;
                    uint2 v = As[rr * PA + cc];
                    ahi[mf][i] = v.x;
                    alo[mf][i] = v.y;
                }
            }
            uint32_t bhi[4][2], blo[4][2];
#pragma unroll
            for (int nf = 0; nf < 4; nf++) {
#pragma unroll
                for (int i = 0; i < 2; i++) {
                    int kk = kb + lr + i * 4;
                    int nn = wn + nf * 8 + lq;
                    uint2 v = Bs[kk * PB + nn];
                    bhi[nf][i] = v.x;
                    blo[nf][i] = v.y;
                }
            }
#pragma unroll
            for (int mf = 0; mf < 2; mf++)
#pragma unroll
                for (int nf = 0; nf < 4; nf++) {
                    mma8(acc[mf][nf], ahi[mf], bhi[nf]);
                    mma8(acc[mf][nf], ahi[mf], blo[nf]);
                    mma8(acc[mf][nf], alo[mf], bhi[nf]);
                }
        }
        __syncthreads();
    }

    // ---- epilogue: bias (+Cin) (+relu), float2 stores ----
#pragma unroll
    for (int mf = 0; mf < 2; mf++) {
#pragma unroll
        for (int nf = 0; nf < 4; nf++) {
            int c = col0 + wn + nf * 8 + 2 * lr;
            if (c >= NN) continue;
            float b0 = bias[c], b1 = bias[c + 1];
#pragma unroll
            for (int half = 0; half < 2; half++) {
                int r = row0 + wm + mf * 16 + lq + half * 8;
                float v0 = acc[mf][nf][half * 2 + 0] + b0;
                float v1 = acc[mf][nf][half * 2 + 1] + b1;
                if (ADD_C) {
                    const float2 ci = *(const float2*)&Cin[(size_t)r * NN + c];
                    v0 += ci.x; v1 += ci.y;
                }
                if (RELU) { v0 = fmaxf(v0, 0.f); v1 = fmaxf(v1, 0.f); }
                *(float2*)&Cout[(size_t)r * NN + c] = make_float2(v0, v1);
            }
        }
    }
}

// ---------------------------------------------------------------------------
// Final pooling: z[g][j] = mu_g + exp(0.5*lv_g)*eps
// ---------------------------------------------------------------------------
__global__ void k_pool(const float* __restrict__ mu, const float* __restrict__ lv,
                       const float* __restrict__ w, const float* __restrict__ eps,
                       const int* __restrict__ gptr, float* __restrict__ out) {
    int g = blockIdx.x;
    int j = threadIdx.x;
    if (j >= NN) return;
    int s = gptr[g], e = gptr[g + 1];
    float ms = 0.f, ls = 0.f;
    for (int n = s; n < e; n++) {
        float ww = w[n];
        ms += mu[(size_t)n * NN + j] * ww;
        ls += lv[(size_t)n * NN + j] * ww;
    }
    float c = fmaxf((float)(e - s), 1.f);
    out[(size_t)g * NN + j] = ms / c + expf(0.5f * ls / c) * eps[(size_t)g * NN + j];
}

// ---------------------------------------------------------------------------
// Host orchestration
// ---------------------------------------------------------------------------
static void* sym(const void* s) {
    void* p = nullptr;
    cudaGetSymbolAddress(&p, (const void*)s);
    return p;
}

extern "C" void kernel_launch(void* const* d_in, const int* in_sizes, int n_in,
                              void* d_out, int out_size) {
    const float* x         = (const float*)d_in[0];
    const float* edge_attr = (const float*)d_in[1];
    const float* W_atoms   = (const float*)d_in[2];
    const float* eps       = (const float*)d_in[3];
    const int*   src_half  = (const int*)d_in[4];
    const int*   dst_half  = (const int*)d_in[5];
    const int*   batch     = (const int*)d_in[6];
    const float* t_lin_w   = (const float*)d_in[7];
    const float* t_lin_b   = (const float*)d_in[8];
    const float* t_mp_w    = (const float*)d_in[9];
    const float* t_mp_b    = (const float*)d_in[10];
    const float* t_au_w    = (const float*)d_in[11];
    const float* t_au_b    = (const float*)d_in[12];
    const float* mu_lin_w  = (const float*)d_in[13];
    const float* mu_lin_b  = (const float*)d_in[14];
    const float* mu_mp_w   = (const float*)d_in[15];
    const float* mu_mp_b   = (const float*)d_in[16];
    const float* mu_au_w   = (const float*)d_in[17];
    const float* mu_au_b   = (const float*)d_in[18];
    const float* lv_lin_w  = (const float*)d_in[19];
    const float* lv_lin_b  = (const float*)d_in[20];
    const float* lv_mp_w   = (const float*)d_in[21];
    const float* lv_mp_b   = (const float*)d_in[22];
    const float* lv_au_w   = (const float*)d_in[23];
    const float* lv_au_b   = (const float*)d_in[24];
    float* out = (float*)d_out;
    (void)in_sizes; (void)n_in; (void)out_size;

    float* h      = (float*)sym(g_h);
    float* h2     = (float*)sym(g_h2);
    float* nacc   = (float*)sym(g_nacc);
    float* shrd   = (float*)sym(g_shared);
    float* mu     = (float*)sym(g_mu);
    float* lv     = (float*)sym(g_lv);
    int* src      = (int*)sym(g_src);
    int* dst      = (int*)sym(g_dst);
    int* deg      = (int*)sym(g_deg);
    int* rowptr   = (int*)sym(g_rowptr);
    int* cursor   = (int*)sym(g_cursor);
    int* eidx     = (int*)sym(g_eidx);
    int* gcnt     = (int*)sym(g_gcnt);
    int* gptr     = (int*)sym(g_gptr);

    // Opt in to 54 KB dynamic smem for all GEMM instantiations (idempotent).
    cudaFuncSetAttribute(k_gemm_tc<1, true,  false>, cudaFuncAttributeMaxDynamicSharedMemorySize, GEMM_SMEM);
    cudaFuncSetAttribute(k_gemm_tc<3, true,  true >, cudaFuncAttributeMaxDynamicSharedMemorySize, GEMM_SMEM);
    cudaFuncSetAttribute(k_gemm_tc<2, true,  false>, cudaFuncAttributeMaxDynamicSharedMemorySize, GEMM_SMEM);
    cudaFuncSetAttribute(k_gemm_tc<2, false, false>, cudaFuncAttributeMaxDynamicSharedMemorySize, GEMM_SMEM);

    const int TPB = 256;

    // ---- CSR build (incoming edges per node) ----
    k_edges<<<(HALF_E + TPB - 1) / TPB, TPB>>>(src_half, dst_half, src, dst, HALF_E);
    k_zero_int<<<(N_NODES + TPB - 1) / TPB, TPB>>>(deg, N_NODES);
    k_count<<<(N_EDGES + TPB - 1) / TPB, TPB>>>(dst, deg, N_EDGES);
    k_scan<<<1, 1024>>>(deg, rowptr, N_NODES);
    cudaMemcpyAsync(cursor, rowptr, N_NODES * sizeof(int), cudaMemcpyDeviceToDevice);
    k_fill_csr<<<(N_EDGES + TPB - 1) / TPB, TPB>>>(dst, cursor, eidx, N_EDGES);

    // ---- graph segment offsets (batch is sorted) ----
    k_zero_int<<<(N_GRAPHS + TPB - 1) / TPB, TPB>>>(gcnt, N_GRAPHS);
    k_count<<<(N_NODES + TPB - 1) / TPB, TPB>>>(batch, gcnt, N_NODES);
    k_scan<<<1, 1024>>>(gcnt, gptr, N_GRAPHS);

    dim3 gridE((NN + 63) / 64, N_EDGES / 128);   // x = col tiles (fast) -> L2 reuse of A
    dim3 gridN((NN + 63) / 64, N_NODES / 128);

    // ---- one conv layer ----
    auto conv = [&](const float* node_in, int dnode,
                    const float* lin_w, const float* lin_b,
                    const float* mp_w, const float* mp_b,
                    const float* au_w, const float* au_b,
                    float* outbuf, bool out_relu) {
        float* ha = h;   // current
        float* hb = h2;  // next

        // ha = relu([node_in[src], edge_attr] @ lin_w + lin_b)
        k_gemm_tc<1, true, false><<<gridE, 256, GEMM_SMEM>>>(
            node_in, edge_attr, src,
            N_EDGES, dnode + EDGE_DIM, dnode, EDGE_DIM,
            lin_w, lin_b, nullptr, ha);

        for (int i = 0; i < 3; i++) {
            k_segsum<<<N_NODES, 320>>>(ha, rowptr, eidx, nacc);
            // hb = relu(ha + (nacc[src] - ha[rev]) @ mp_w[i] + mp_b[i])  (agg fused)
            k_gemm_tc<3, true, true><<<gridE, 256, GEMM_SMEM>>>(
                nacc, ha, src,
                N_EDGES, HID, 0, 0,
                mp_w + (size_t)i * HID * HID, mp_b + (size_t)i * HID, ha, hb);
            float* t = ha; ha = hb; hb = t;
        }

        // sum_inc -> nacc; out = act([node_in, sum_inc] @ au_w + au_b)
        k_segsum<<<N_NODES, 320>>>(ha, rowptr, eidx, nacc);
        if (out_relu)
            k_gemm_tc<2, true, false><<<gridN, 256, GEMM_SMEM>>>(
                node_in, nacc, nullptr,
                N_NODES, dnode + HID, dnode, HID,
                au_w, au_b, nullptr, outbuf);
        else
            k_gemm_tc<2, false, false><<<gridN, 256, GEMM_SMEM>>>(
                node_in, nacc, nullptr,
                N_NODES, dnode + HID, dnode, HID,
                au_w, au_b, nullptr, outbuf);
    };

    conv(x,    NODE_DIM, t_lin_w,  t_lin_b,  t_mp_w,  t_mp_b,  t_au_w,  t_au_b,  shrd, true);
    conv(shrd, HID,      mu_lin_w, mu_lin_b, mu_mp_w, mu_mp_b, mu_au_w, mu_au_b, mu,   false);
    conv(shrd, HID,      lv_lin_w, lv_lin_b, lv_mp_w, lv_mp_b, lv_au_w, lv_au_b, lv,   false);

    k_pool<<<N_GRAPHS, 320>>>(mu, lv, W_atoms, eps, gptr, out);
}

// round 5
// speedup vs baseline: 1.8871x; 1.3647x over previous
#include <cuda_runtime.h>
#include <cuda_fp16.h>
#include <math.h>
#include <stdint.h>

// Problem constants
#define N_NODES   80000
#define N_EDGES   160000
#define HALF_E    80000
#define HID       300
#define NODE_DIM  133
#define EDGE_DIM  14
#define N_GRAPHS  1600
#define NN        300   // output columns of every GEMM

// ---------------------------------------------------------------------------
// Device scratch
// ---------------------------------------------------------------------------
__device__ float g_h[(size_t)N_EDGES * HID];
__device__ float g_h2[(size_t)N_EDGES * HID];
__device__ float g_nacc[(size_t)N_NODES * HID];
__device__ float g_shared[(size_t)N_NODES * HID];
__device__ float g_mu[(size_t)N_NODES * HID];
__device__ float g_lv[(size_t)N_NODES * HID];

__device__ int g_src[N_EDGES];
__device__ int g_dst[N_EDGES];
__device__ int g_deg[N_NODES];
__device__ int g_rowptr[N_NODES + 1];
__device__ int g_cursor[N_NODES];
__device__ int g_eidx[N_EDGES];
__device__ int g_gcnt[N_GRAPHS];
__device__ int g_gptr[N_GRAPHS + 1];

// ---------------------------------------------------------------------------
// Fused setup kernels
// ---------------------------------------------------------------------------
__global__ void k_zero_all(int* deg, int* gcnt) {
    int i = blockIdx.x * blockDim.x + threadIdx.x;
    if (i < N_NODES) deg[i] = 0;
    if (i < N_GRAPHS) gcnt[i] = 0;
}

__global__ void k_setup(const int* __restrict__ sh, const int* __restrict__ dh,
                        const int* __restrict__ batch,
                        int* __restrict__ src, int* __restrict__ dst,
                        int* __restrict__ deg, int* __restrict__ gcnt) {
    int i = blockIdx.x * blockDim.x + threadIdx.x;
    if (i < HALF_E) {
        int s = sh[i], d = dh[i];
        src[i] = s;          dst[i] = d;
        src[i + HALF_E] = d; dst[i + HALF_E] = s;
        atomicAdd(&deg[d], 1);
        atomicAdd(&deg[s], 1);
    }
    if (i < N_NODES) atomicAdd(&gcnt[batch[i]], 1);
}

__device__ void scan_block(const int* __restrict__ in, int* __restrict__ out,
                           int* __restrict__ copy, int n) {
    __shared__ int sums[1024];
    int t = threadIdx.x;
    int chunk = (n + 1023) / 1024;
    int s = t * chunk;
    int e = s + chunk; if (e > n) e = n; if (s > n) s = n;
    int local = 0;
    for (int i = s; i < e; i++) local += in[i];
    sums[t] = local;
    __syncthreads();
    if (t == 0) {
        int run = 0;
        for (int i = 0; i < 1024; i++) { int v = sums[i]; sums[i] = run; run += v; }
        out[n] = run;
    }
    __syncthreads();
    int run = sums[t];
    for (int i = s; i < e; i++) {
        out[i] = run;
        if (copy) copy[i] = run;
        run += in[i];
    }
}

__global__ void k_scan2(const int* deg, int* rowptr, int* cursor,
                        const int* gcnt, int* gptr) {
    if (blockIdx.x == 0) scan_block(deg, rowptr, cursor, N_NODES);
    else                 scan_block(gcnt, gptr, nullptr, N_GRAPHS);
}

__global__ void k_fill_csr(const int* __restrict__ dst, int* __restrict__ cursor,
                           int* __restrict__ eidx, int n) {
    int e = blockIdx.x * blockDim.x + threadIdx.x;
    if (e < n) {
        int p = atomicAdd(&cursor[dst[e]], 1);
        eidx[p] = e;
    }
}

// node_acc[n][j] = sum over incoming edges e of h[e][j]   (CSR gather)
__global__ void k_segsum(const float* __restrict__ h, const int* __restrict__ rowptr,
                         const int* __restrict__ eidx, float* __restrict__ out) {
    int node = blockIdx.x;
    int j = threadIdx.x;
    if (j >= NN) return;
    int s = rowptr[node], e = rowptr[node + 1];
    float sum = 0.f;
    for (int i = s; i < e; i++)
        sum += h[(size_t)eidx[i] * NN + j];
    out[(size_t)node * NN + j] = sum;
}

// ---------------------------------------------------------------------------
// FP16x3-split tensor-core GEMM (legacy mma.sync m16n8k16, fp32 accumulate).
// C = act( A' @ B + bias (+ Cin) )
// MODE 1: A'[r][k] = (k < d1) ? X[idx[r]*d1 + k] : Y[r*d2 + (k-d1)]    (lin)
// MODE 2: A'[r][k] = (k < d1) ? X[r*d1 + k]      : Y[r*d2 + (k-d1)]    (atom upd)
// MODE 3: A'[r][k] = X[idx[r]*NN + k] - Y[rev(r)*NN + k]               (mp agg)
// v = hi + lo (both fp16); v*w ≈ hi*whi + hi*wlo + lo*whi (err ~2^-22).
// Block tile 128x64, BK=32, 256 threads (8 warps, 4x2 of 32x32 warp tiles).
// Smem: packed half2 (two k's per word), pitch 20 words -> conflict-free frags.
// M must be a multiple of 128.
// ---------------------------------------------------------------------------
#define PW 20   // row pitch in 32-bit words (16 data + 4 pad)

__device__ __forceinline__ void split16(float v, uint16_t& hi, uint16_t& lo) {
    __half h = __float2half_rn(v);
    __half l = __float2half_rn(v - __half2float(h));
    hi = __half_as_ushort(h);
    lo = __half_as_ushort(l);
}

__device__ __forceinline__ void mma16(float* c, const uint32_t* a,
                                      const uint32_t* b) {
    asm volatile(
        "mma.sync.aligned.m16n8k16.row.col.f32.f16.f16.f32 "
        "{%0,%1,%2,%3}, {%4,%5,%6,%7}, {%8,%9}, {%0,%1,%2,%3};\n"
        : "+f"(c[0]), "+f"(c[1]), "+f"(c[2]), "+f"(c[3])
        : "r"(a[0]), "r"(a[1]), "r"(a[2]), "r"(a[3]), "r"(b[0]), "r"(b[1]));
}

template <int MODE, bool RELU, bool ADD_C>
__global__ __launch_bounds__(256, 2)
void k_gemm_f16(const float* __restrict__ X, const float* __restrict__ Y,
                const int* __restrict__ idx, int M, int K, int d1, int d2,
                const float* __restrict__ B, const float* __restrict__ bias,
                const float* __restrict__ Cin, float* __restrict__ Cout) {
    __shared__ uint32_t AsHi[128 * PW];
    __shared__ uint32_t AsLo[128 * PW];
    __shared__ uint32_t BsHi[64 * PW];
    __shared__ uint32_t BsLo[64 * PW];

    const int tid  = threadIdx.x;
    const int warp = tid >> 5;
    const int lane = tid & 31;
    const int wm = (warp >> 1) * 32;   // 0,32,64,96
    const int wn = (warp & 1) * 32;    // 0,32
    const int row0 = blockIdx.y * 128;
    const int col0 = blockIdx.x * 64;
    const int lq = lane >> 2;          // 0..7
    const int lr = lane & 3;           // 0..3

    float acc[2][4][4];
#pragma unroll
    for (int mf = 0; mf < 2; mf++)
#pragma unroll
        for (int nf = 0; nf < 4; nf++)
#pragma unroll
            for (int i = 0; i < 4; i++) acc[mf][nf][i] = 0.f;

    for (int k0 = 0; k0 < K; k0 += 32) {
        // ---- A tile: 128 rows x 32 k (16 words). thread: word=tid&15 ----
        {
            const int kw  = tid & 15;
            const int gk0 = k0 + kw * 2;
            const int rg  = tid >> 4;         // 0..15
#pragma unroll
            for (int p = 0; p < 8; p++) {
                const int m = rg + p * 16;
                const int r = row0 + m;
                float v0 = 0.f, v1 = 0.f;
                if (MODE == 3) {
                    if (gk0 < K) {   // K==NN==300 even, gk0 even -> pair in-row
                        const int re = (r < HALF_E) ? r + HALF_E : r - HALF_E;
                        const float2 xa = *(const float2*)&X[(size_t)idx[r] * NN + gk0];
                        const float2 ya = *(const float2*)&Y[(size_t)re * NN + gk0];
                        v0 = xa.x - ya.x;
                        v1 = xa.y - ya.y;
                    }
                } else {
#pragma unroll
                    for (int u = 0; u < 2; u++) {
                        const int gk = gk0 + u;
                        float v = 0.f;
                        if (gk < K) {
                            if (MODE == 1) v = (gk < d1) ? X[(size_t)idx[r] * d1 + gk]
                                                         : Y[(size_t)r * d2 + (gk - d1)];
                            else           v = (gk < d1) ? X[(size_t)r * d1 + gk]
                                                         : Y[(size_t)r * d2 + (gk - d1)];
                        }
                        if (u == 0) v0 = v; else v1 = v;
                    }
                }
                uint16_t h0, l0, h1, l1;
                split16(v0, h0, l0);
                split16(v1, h1, l1);
                AsHi[m * PW + kw] = (uint32_t)h0 | ((uint32_t)h1 << 16);
                AsLo[m * PW + kw] = (uint32_t)l0 | ((uint32_t)l1 << 16);
            }
        }
        // ---- B tile: 64 n x 32 k. thread: n = tid&63 (coalesced over n) ----
        {
            const int n  = tid & 63;
            const int cc = col0 + n;
            const bool nok = (cc < NN);
#pragma unroll
            for (int p = 0; p < 4; p++) {
                const int kw = (tid >> 6) + p * 4;   // word 0..15
                const int gk = k0 + kw * 2;
                float v0 = 0.f, v1 = 0.f;
                if (nok) {
                    if (gk < K)     v0 = B[(size_t)gk * NN + cc];
                    if (gk + 1 < K) v1 = B[(size_t)(gk + 1) * NN + cc];
                }
                uint16_t h0, l0, h1, l1;
                split16(v0, h0, l0);
                split16(v1, h1, l1);
                BsHi[n * PW + kw] = (uint32_t)h0 | ((uint32_t)h1 << 16);
                BsLo[n * PW + kw] = (uint32_t)l0 | ((uint32_t)l1 << 16);
            }
        }
        __syncthreads();

#pragma unroll
        for (int s = 0; s < 2; s++) {           // two k16 steps per chunk
            const int wb = s * 8;               // word base
            uint32_t ahi[2][4], alo[2][4];
#pragma unroll
            for (int mf = 0; mf < 2; mf++) {
                const int r0 = (wm + mf * 16 + lq) * PW;
                const int r8 = r0 + 8 * PW;
                ahi[mf][0] = AsHi[r0 + wb + lr];
                ahi[mf][1] = AsHi[r8 + wb + lr];
                ahi[mf][2] = AsHi[r0 + wb + lr + 4];
                ahi[mf][3] = AsHi[r8 + wb + lr + 4];
                alo[mf][0] = AsLo[r0 + wb + lr];
                alo[mf][1] = AsLo[r8 + wb + lr];
                alo[mf][2] = AsLo[r0 + wb + lr + 4];
                alo[mf][3] = AsLo[r8 + wb + lr + 4];
            }
            uint32_t bhi[4][2], blo[4][2];
#pragma unroll
            for (int nf = 0; nf < 4; nf++) {
                const int nb = (wn + nf * 8 + lq) * PW;
                bhi[nf][0] = BsHi[nb + wb + lr];
                bhi[nf][1] = BsHi[nb + wb + lr + 4];
                blo[nf][0] = BsLo[nb + wb + lr];
                blo[nf][1] = BsLo[nb + wb + lr + 4];
            }
            // term-major: 8 independent mmas between same-acc dependences
#pragma unroll
            for (int mf = 0; mf < 2; mf++)
#pragma unroll
                for (int nf = 0; nf < 4; nf++)
                    mma16(acc[mf][nf], ahi[mf], bhi[nf]);
#pragma unroll
            for (int mf = 0; mf < 2; mf++)
#pragma unroll
                for (int nf = 0; nf < 4; nf++)
                    mma16(acc[mf][nf], ahi[mf], blo[nf]);
#pragma unroll
            for (int mf = 0; mf < 2; mf++)
#pragma unroll
                for (int nf = 0; nf < 4; nf++)
                    mma16(acc[mf][nf], alo[mf], bhi[nf]);
        }
        __syncthreads();
    }

    // ---- epilogue: bias (+Cin) (+relu), float2 stores ----
#pragma unroll
    for (int mf = 0; mf < 2; mf++) {
#pragma unroll
        for (int nf = 0; nf < 4; nf++) {
            int c = col0 + wn + nf * 8 + 2 * lr;
            if (c >= NN) continue;
            float b0 = bias[c], b1 = bias[c + 1];
#pragma unroll
            for (int half = 0; half < 2; half++) {
                int r = row0 + wm + mf * 16 + lq + half * 8;
                float v0 = acc[mf][nf][half * 2 + 0] + b0;
                float v1 = acc[mf][nf][half * 2 + 1] + b1;
                if (ADD_C) {
                    const float2 ci = *(const float2*)&Cin[(size_t)r * NN + c];
                    v0 += ci.x; v1 += ci.y;
                }
                if (RELU) { v0 = fmaxf(v0, 0.f); v1 = fmaxf(v1, 0.f); }
                *(float2*)&Cout[(size_t)r * NN + c] = make_float2(v0, v1);
            }
        }
    }
}

// ---------------------------------------------------------------------------
// Final pooling: z[g][j] = mu_g + exp(0.5*lv_g)*eps
// ---------------------------------------------------------------------------
__global__ void k_pool(const float* __restrict__ mu, const float* __restrict__ lv,
                       const float* __restrict__ w, const float* __restrict__ eps,
                       const int* __restrict__ gptr, float* __restrict__ out) {
    int g = blockIdx.x;
    int j = threadIdx.x;
    if (j >= NN) return;
    int s = gptr[g], e = gptr[g + 1];
    float ms = 0.f, ls = 0.f;
    for (int n = s; n < e; n++) {
        float ww = w[n];
        ms += mu[(size_t)n * NN + j] * ww;
        ls += lv[(size_t)n * NN + j] * ww;
    }
    float c = fmaxf((float)(e - s), 1.f);
    out[(size_t)g * NN + j] = ms / c + expf(0.5f * ls / c) * eps[(size_t)g * NN + j];
}

// ---------------------------------------------------------------------------
// Host orchestration
// ---------------------------------------------------------------------------
static void* sym(const void* s) {
    void* p = nullptr;
    cudaGetSymbolAddress(&p, (const void*)s);
    return p;
}

extern "C" void kernel_launch(void* const* d_in, const int* in_sizes, int n_in,
                              void* d_out, int out_size) {
    const float* x         = (const float*)d_in[0];
    const float* edge_attr = (const float*)d_in[1];
    const float* W_atoms   = (const float*)d_in[2];
    const float* eps       = (const float*)d_in[3];
    const int*   src_half  = (const int*)d_in[4];
    const int*   dst_half  = (const int*)d_in[5];
    const int*   batch     = (const int*)d_in[6];
    const float* t_lin_w   = (const float*)d_in[7];
    const float* t_lin_b   = (const float*)d_in[8];
    const float* t_mp_w    = (const float*)d_in[9];
    const float* t_mp_b    = (const float*)d_in[10];
    const float* t_au_w    = (const float*)d_in[11];
    const float* t_au_b    = (const float*)d_in[12];
    const float* mu_lin_w  = (const float*)d_in[13];
    const float* mu_lin_b  = (const float*)d_in[14];
    const float* mu_mp_w   = (const float*)d_in[15];
    const float* mu_mp_b   = (const float*)d_in[16];
    const float* mu_au_w   = (const float*)d_in[17];
    const float* mu_au_b   = (const float*)d_in[18];
    const float* lv_lin_w  = (const float*)d_in[19];
    const float* lv_lin_b  = (const float*)d_in[20];
    const float* lv_mp_w   = (const float*)d_in[21];
    const float* lv_mp_b   = (const float*)d_in[22];
    const float* lv_au_w   = (const float*)d_in[23];
    const float* lv_au_b   = (const float*)d_in[24];
    float* out = (float*)d_out;
    (void)in_sizes; (void)n_in; (void)out_size;

    float* h      = (float*)sym(g_h);
    float* h2     = (float*)sym(g_h2);
    float* nacc   = (float*)sym(g_nacc);
    float* shrd   = (float*)sym(g_shared);
    float* mu     = (float*)sym(g_mu);
    float* lv     = (float*)sym(g_lv);
    int* src      = (int*)sym(g_src);
    int* dst      = (int*)sym(g_dst);
    int* deg      = (int*)sym(g_deg);
    int* rowptr   = (int*)sym(g_rowptr);
    int* cursor   = (int*)sym(g_cursor);
    int* eidx     = (int*)sym(g_eidx);
    int* gcnt     = (int*)sym(g_gcnt);
    int* gptr     = (int*)sym(g_gptr);

    const int TPB = 256;

    // ---- setup: 4 launches ----
    k_zero_all<<<(N_NODES + TPB - 1) / TPB, TPB>>>(deg, gcnt);
    k_setup<<<(N_NODES + TPB - 1) / TPB, TPB>>>(src_half, dst_half, batch,
                                                src, dst, deg, gcnt);
    k_scan2<<<2, 1024>>>(deg, rowptr, cursor, gcnt, gptr);
    k_fill_csr<<<(N_EDGES + TPB - 1) / TPB, TPB>>>(dst, cursor, eidx, N_EDGES);

    dim3 gridE((NN + 63) / 64, N_EDGES / 128);   // x = col tiles fast -> L2 reuse of A
    dim3 gridN((NN + 63) / 64, N_NODES / 128);

    // ---- one conv layer ----
    auto conv = [&](const float* node_in, int dnode,
                    const float* lin_w, const float* lin_b,
                    const float* mp_w, const float* mp_b,
                    const float* au_w, const float* au_b,
                    float* outbuf, bool out_relu) {
        float* ha = h;
        float* hb = h2;

        // ha = relu([node_in[src], edge_attr] @ lin_w + lin_b)
        k_gemm_f16<1, true, false><<<gridE, 256>>>(
            node_in, edge_attr, src,
            N_EDGES, dnode + EDGE_DIM, dnode, EDGE_DIM,
            lin_w, lin_b, nullptr, ha);

        for (int i = 0; i < 3; i++) {
            k_segsum<<<N_NODES, 320>>>(ha, rowptr, eidx, nacc);
            // hb = relu(ha + (nacc[src] - ha[rev]) @ mp_w[i] + mp_b[i])
            k_gemm_f16<3, true, true><<<gridE, 256>>>(
                nacc, ha, src,
                N_EDGES, HID, 0, 0,
                mp_w + (size_t)i * HID * HID, mp_b + (size_t)i * HID, ha, hb);
            float* t = ha; ha = hb; hb = t;
        }

        k_segsum<<<N_NODES, 320>>>(ha, rowptr, eidx, nacc);
        if (out_relu)
            k_gemm_f16<2, true, false><<<gridN, 256>>>(
                node_in, nacc, nullptr,
                N_NODES, dnode + HID, dnode, HID,
                au_w, au_b, nullptr, outbuf);
        else
            k_gemm_f16<2, false, false><<<gridN, 256>>>(
                node_in, nacc, nullptr,
                N_NODES, dnode + HID, dnode, HID,
                au_w, au_b, nullptr, outbuf);
    };

    conv(x,    NODE_DIM, t_lin_w,  t_lin_b,  t_mp_w,  t_mp_b,  t_au_w,  t_au_b,  shrd, true);
    conv(shrd, HID,      mu_lin_w, mu_lin_b, mu_mp_w, mu_mp_b, mu_au_w, mu_au_b, mu,   false);
    conv(shrd, HID,      lv_lin_w, lv_lin_b, lv_mp_w, lv_mp_b, lv_au_w, lv_au_b, lv,   false);

    k_pool<<<N_GRAPHS, 320>>>(mu, lv, W_atoms, eps, gptr, out);
}